// round 5
// baseline (speedup 1.0000x reference)
#include <cuda_runtime.h>
#include <math.h>

#define BB 2
#define MM 4096
#define CC 256
#define HW 64
#define NBINS 512                // 2 batches * 16 * 16
#define QCAP 96
#define NPOS_MAX 169             // 13*13 at level 0
#define PSTRH 132                // padded half-row stride (floats): conflict-free
#define DSTR 172

// padded pyramid: halo x,y in [-4, Wl+4] -> dims (Wl+9)^2 per level
// L0 73^2=5329, L1 41^2=1681, L2 25^2=625, L3 17^2=289 ; total 7924 positions
#define PW0 73
#define PW1 41
#define PW2 25
#define PW3 17
#define TOTPOS 7924
// layout: [b][h][pos][128]
__device__ float g_pyr2[BB * 2 * TOTPOS * 128];
__device__ int   g_cnt[NBINS];
__device__ int   g_qlist[NBINS * QCAP];

__constant__ int c_lvl_base[4] = {0, 5329, 7010, 7635};
__constant__ int c_lvl_pw[4]   = {PW0, PW1, PW2, PW3};

// ---------------- helpers ---------------------------------------------------
__device__ __forceinline__ void fma2(unsigned long long& d,
                                     unsigned long long a,
                                     unsigned long long b) {
    asm("fma.rn.f32x2 %0, %1, %2, %0;" : "+l"(d) : "l"(a), "l"(b));
}
__device__ __forceinline__ float unpack_sum(unsigned long long v) {
    return __uint_as_float((unsigned)v) + __uint_as_float((unsigned)(v >> 32));
}
__device__ __forceinline__ void bulkcp(unsigned dst, const void* src,
                                       unsigned bytes, unsigned mbar) {
    asm volatile(
        "cp.async.bulk.shared::cluster.global.mbarrier::complete_tx::bytes "
        "[%0], [%1], %2, [%3];"
        :: "r"(dst), "l"(src), "r"(bytes), "r"(mbar) : "memory");
}
__device__ __forceinline__ void mbar_init(unsigned mbar, unsigned cnt) {
    asm volatile("mbarrier.init.shared.b64 [%0], %1;" :: "r"(mbar), "r"(cnt) : "memory");
}
__device__ __forceinline__ void mbar_expect(unsigned mbar, unsigned bytes) {
    asm volatile("mbarrier.arrive.expect_tx.shared.b64 _, [%0], %1;"
                 :: "r"(mbar), "r"(bytes) : "memory");
}
__device__ __forceinline__ void mbar_wait(unsigned mbar, unsigned parity) {
    unsigned done;
    asm volatile(
        "{\n\t.reg .pred p;\n\t"
        "mbarrier.try_wait.parity.shared.b64 p, [%1], %2;\n\t"
        "selp.b32 %0, 1, 0, p;\n\t}"
        : "=r"(done) : "r"(mbar), "r"(parity) : "memory");
    while (!done) {
        asm volatile(
            "{\n\t.reg .pred p;\n\t"
            "mbarrier.try_wait.parity.shared.b64 p, [%1], %2, 0x989680;\n\t"
            "selp.b32 %0, 1, 0, p;\n\t}"
            : "=r"(done) : "r"(mbar), "r"(parity) : "memory");
    }
}

// ---------------- zero the padded pyramid (halo must be 0) ------------------
__global__ void zero_pyr_kernel() {
    float4* p = (float4*)g_pyr2;
    int n = BB * 2 * TOTPOS * 32;   // float4 count
    for (int i = blockIdx.x * blockDim.x + threadIdx.x; i < n; i += gridDim.x * blockDim.x)
        p[i] = make_float4(0.f, 0.f, 0.f, 0.f);
}

// ---------------- transpose fmap2 (B,C,H,W) -> padded L0 [b][h][pos][128] ---
__global__ void transpose_kernel(const float* __restrict__ f2) {
    __shared__ float tile[32][33];
    int b  = blockIdx.z;
    int p0 = blockIdx.x * 32;   // spatial
    int c0 = blockIdx.y * 32;   // channels
    int tx = threadIdx.x, ty = threadIdx.y;
    tile[ty][tx] = f2[((size_t)b * CC + (c0 + ty)) * (HW * HW) + p0 + tx];
    __syncthreads();
    int p = p0 + ty;
    int y = p >> 6, x = p & 63;
    int c = c0 + tx;
    int h = c >> 7, cc = c & 127;
    int pos = (y + 4) * PW0 + (x + 4);
    g_pyr2[((size_t)(b * 2 + h) * TOTPOS + pos) * 128 + cc] = tile[tx][ty];
}

// ---------------- 2x2 avg pool (padded layout, both halves) -----------------
__global__ void pool_kernel(int lin, int lout, int Wout) {
    int c = threadIdx.x;                // 256: channel
    int h = c >> 7, cc = c & 127;
    int r = blockIdx.x;
    int b = r / (Wout * Wout); r -= b * Wout * Wout;
    int y = r / Wout, x = r - (r / Wout) * Wout;
    int pwi = c_lvl_pw[lin], pwo = c_lvl_pw[lout];
    const float* in = g_pyr2 + ((size_t)(b * 2 + h) * TOTPOS + c_lvl_base[lin]) * 128 + cc;
    float* out      = g_pyr2 + ((size_t)(b * 2 + h) * TOTPOS + c_lvl_base[lout]) * 128 + cc;
    int y2 = 2 * y + 4, x2 = 2 * x + 4;
    float v = 0.25f * (in[(size_t)((y2)     * pwi + x2)     * 128]
                     + in[(size_t)((y2)     * pwi + x2 + 1) * 128]
                     + in[(size_t)((y2 + 1) * pwi + x2)     * 128]
                     + in[(size_t)((y2 + 1) * pwi + x2 + 1) * 128]);
    out[(size_t)((y + 4) * pwo + (x + 4)) * 128] = v;
}

__global__ void zero_cnt_kernel() {
    if (threadIdx.x < NBINS) g_cnt[threadIdx.x] = 0;
}

__global__ void hist_kernel(const float* __restrict__ cen) {
    int t = blockIdx.x * blockDim.x + threadIdx.x;
    if (t >= BB * MM) return;
    float cx = cen[2 * t], cy = cen[2 * t + 1];
    int bx = ((int)cx) >> 2;  bx = bx < 0 ? 0 : (bx > 15 ? 15 : bx);
    int by = ((int)cy) >> 2;  by = by < 0 ? 0 : (by > 15 ? 15 : by);
    int b = t / MM, m = t - b * MM;
    int bin = (b << 8) | (by << 4) | bx;
    int pos = atomicAdd(&g_cnt[bin], 1);
    if (pos < QCAP) g_qlist[bin * QCAP + pos] = m;
}

// ---------------- main: per-(bin,level) register-tiled GEMM ------------------
// Staging via cp.async.bulk (512 B per position/query half) + mbarrier.
// K split in two 128-ch halves (pyramid stored pre-split); acc in registers.
__global__ __launch_bounds__(256) void corr_kernel(const float* __restrict__ f1,
                                                   const float* __restrict__ cen,
                                                   float* __restrict__ out) {
    extern __shared__ float sm[];
    float* Ps = sm;                           // NPOS_MAX * PSTRH
    float* As = sm + NPOS_MAX * PSTRH;        // 16 * PSTRH
    float* Ds = As + 16 * PSTRH;              // 16 * DSTR
    __shared__ __align__(8) unsigned long long mbar_s;

    int blk = blockIdx.x;
    int lvl = blk & 3;
    int bin = blk >> 2;
    int b  = bin >> 8;
    int by = (bin >> 4) & 15, bx = bin & 15;
    int nq = g_cnt[bin]; if (nq > QCAP) nq = QCAP;
    if (nq == 0) return;

    int ixmin = (4 * bx) >> lvl, ixmax = (4 * bx + 3) >> lvl;
    int iymin = (4 * by) >> lvl, iymax = (4 * by + 3) >> lvl;
    int px0 = ixmin - 4, py0 = iymin - 4;
    int pw = ixmax - ixmin + 10, ph = iymax - iymin + 10;
    int Npos = pw * ph;
    int pwp = c_lvl_pw[lvl];

    int tid = threadIdx.x, lane = tid & 31, w = tid >> 5;
    int qsel = lane >> 3;        // 0..3
    int psel = lane & 7;         // 0..7
    int wbase = w * 32;
    float scale = 1.0f / (float)(1 << lvl);

    unsigned Ps_b = (unsigned)__cvta_generic_to_shared(Ps);
    unsigned As_b = (unsigned)__cvta_generic_to_shared(As);
    unsigned mbar = (unsigned)__cvta_generic_to_shared(&mbar_s);

    if (tid == 0) mbar_init(mbar, 1);
    __syncthreads();
    unsigned par = 0;

    int pidx[4];
    #pragma unroll
    for (int pi = 0; pi < 4; pi++) {
        int p = wbase + psel + 8 * pi;
        pidx[pi] = (p < Npos) ? p : (Npos - 1);
    }

    for (int q0 = 0; q0 < nq; q0 += 16) {
        int qcnt = nq - q0; if (qcnt > 16) qcnt = 16;

        unsigned long long acc[4][4];
        #pragma unroll
        for (int qi = 0; qi < 4; qi++)
            #pragma unroll
            for (int pi = 0; pi < 4; pi++) acc[qi][pi] = 0ull;

        for (int h = 0; h < 2; h++) {
            __syncthreads();   // previous phase's smem fully consumed
            if (tid == 0) mbar_expect(mbar, (unsigned)(Npos + 16) * 512u);

            // patch base: position (px0, py0) in padded level (halo offset +4)
            const float* pbase = g_pyr2
                + ((size_t)(b * 2 + h) * TOTPOS + c_lvl_base[lvl]
                   + (size_t)(py0 + 4) * pwp + (px0 + 4)) * 128;
            int nops = Npos + 16;
            for (int i = tid; i < nops; i += 256) {
                if (i < Npos) {
                    int ly = i / pw, lx = i - (i / pw) * pw;
                    bulkcp(Ps_b + (unsigned)(i * PSTRH) * 4u,
                           pbase + ((size_t)ly * pwp + lx) * 128, 512u, mbar);
                } else {
                    int qq = i - Npos;
                    int qv = (qq < qcnt) ? qq : 0;
                    int m = g_qlist[bin * QCAP + q0 + qv];
                    bulkcp(As_b + (unsigned)(qq * PSTRH) * 4u,
                           f1 + ((size_t)b * MM + m) * CC + h * 128, 512u, mbar);
                }
            }
            mbar_wait(mbar, par);
            par ^= 1;

            // ---- GEMM half: 4q x 4pos per thread, f32x2 -------------------
            if (wbase < Npos) {
                #pragma unroll 2
                for (int c = 0; c < 128; c += 4) {
                    ulonglong2 a[4], p[4];
                    #pragma unroll
                    for (int qi = 0; qi < 4; qi++)
                        a[qi] = *(const ulonglong2*)&As[(qsel + 4 * qi) * PSTRH + c];
                    #pragma unroll
                    for (int pi = 0; pi < 4; pi++)
                        p[pi] = *(const ulonglong2*)&Ps[pidx[pi] * PSTRH + c];
                    #pragma unroll
                    for (int qi = 0; qi < 4; qi++)
                        #pragma unroll
                        for (int pi = 0; pi < 4; pi++) {
                            fma2(acc[qi][pi], a[qi].x, p[pi].x);
                            fma2(acc[qi][pi], a[qi].y, p[pi].y);
                        }
                }
            }
        }

        // ---- write D -------------------------------------------------------
        if (wbase < Npos) {
            #pragma unroll
            for (int qi = 0; qi < 4; qi++)
                #pragma unroll
                for (int pi = 0; pi < 4; pi++) {
                    int p = wbase + psel + 8 * pi;
                    if (p < Npos)
                        Ds[(qsel + 4 * qi) * DSTR + p] = unpack_sum(acc[qi][pi]);
                }
        }
        __syncthreads();

        // ---- bilinear epilogue: warp per query -----------------------------
        for (int qq = w; qq < qcnt; qq += 8) {
            int m = g_qlist[bin * QCAP + q0 + qq];
            float cx = cen[((size_t)b * MM + m) * 2 + 0];
            float cy = cen[((size_t)b * MM + m) * 2 + 1];
            float sx = cx * scale, sy = cy * scale;
            float fix = floorf(sx), fiy = floorf(sy);
            float fx = sx - fix, fy = sy - fiy;
            int ox = (int)fix - 4 - px0;
            int oy = (int)fiy - 4 - py0;
            float wx1 = fx, wx0 = 1.f - fx, wy1 = fy, wy0 = 1.f - fy;
            const float* Dq = Ds + qq * DSTR;
            for (int e = lane; e < 81; e += 32) {
                int i = e / 9, j = e - (e / 9) * 9;   // x-offset i-4, y-offset j-4
                int base = (oy + j) * pw + (ox + i);
                float d00 = Dq[base],      d01 = Dq[base + 1];
                float d10 = Dq[base + pw], d11 = Dq[base + pw + 1];
                float val = wy0 * (wx0 * d00 + wx1 * d01)
                          + wy1 * (wx0 * d10 + wx1 * d11);
                out[((size_t)b * 324 + lvl * 81 + e) * MM + m] = val;
            }
        }
    }
}

// ---------------- launch ----------------------------------------------------
extern "C" void kernel_launch(void* const* d_in, const int* in_sizes, int n_in,
                              void* d_out, int out_size) {
    const float* f1  = (const float*)d_in[0];
    const float* f2  = (const float*)d_in[1];
    const float* cen = (const float*)d_in[2];
    float* out = (float*)d_out;

    size_t smem = (size_t)(NPOS_MAX * PSTRH + 16 * PSTRH + 16 * DSTR) * sizeof(float);
    cudaFuncSetAttribute(corr_kernel, cudaFuncAttributeMaxDynamicSharedMemorySize,
                         (int)smem);

    zero_pyr_kernel<<<1024, 256>>>();
    transpose_kernel<<<dim3(HW * HW / 32, CC / 32, BB), dim3(32, 32)>>>(f2);
    pool_kernel<<<BB * 32 * 32, 256>>>(0, 1, 32);
    pool_kernel<<<BB * 16 * 16, 256>>>(1, 2, 16);
    pool_kernel<<<BB * 8 * 8,   256>>>(2, 3, 8);
    zero_cnt_kernel<<<1, 512>>>();
    hist_kernel<<<(BB * MM + 255) / 256, 256>>>(cen);
    corr_kernel<<<NBINS * 4, 256, smem>>>(f1, cen, out);
}